// round 16
// baseline (speedup 1.0000x reference)
#include <cuda_runtime.h>
#include <cstdint>

// HolographicFMLayer: batched all-pairs circular convolution.
// inputs: float32 [B, 24, 64]  ->  out: float32 [B, 276, 64]
// out[b,p,n] = sum_k x[b,i,k] * x[b,j,(n-k) mod 64], pairs = triu_indices(24, k=1)
//
// CRT split: x^64-1 = (x^16-1)(x^16+1)(x^32+1)
//   per field: u = lo+hi, v = (lo-hi)/sqrt2; P=(u_lo+u_hi)/2, Q=(u_lo-u_hi)/2
//   per pair : d1 = cyclic16(P), d2 = negacyclic16(Q), c2 = negacyclic32(v)
//   recon    : c1[n<16]=d1+d2, c1[16..31]=d1-d2; out[n<32]=c1+c2, out[n+32]=c1-c2
//
// R15: PAIR-AXIS PACKING. Each thread computes 8 outputs for TWO pairs with
// fma.rn.f32x2; every packed reg is (val_pair1, val_pair2) at the same
// position. Window slots rebuild from two fresh scalar LDS (no old-component
// reads — the R5 poison), whole-reg static rotation w[(q-k)&7] (no shifts —
// the R2 poison). 4 threads per pair-duo: role (conv type / c2 half) x
// output-half. Halves the fma-pipe cycles vs the 67us scalar kernel.

#define NF 24
#define NPAIR 276
#define LEN 64
#define THREADS 192
#define DUOS_PER_BLOCK 46       // 3 blocks per batch: 138 duos = 276 pairs exact
#define ACTIVE (DUOS_PER_BLOCK * 4)
#define SV 65                   // 64-entry rows: 65 mod 32 == 1
#define SP 33                   // 32-entry rows: 33 mod 32 == 1
#define OFF_P (NF * SV)                 // 1560
#define OFF_Q (OFF_P + NF * SP + 24)    // +24 pad: (OFF_Q-OFF_P) mod 32 == 16
#define SMEM_FLOATS (OFF_Q + NF * SP)

typedef unsigned long long ull;

// constexpr-built triu pair table in constant memory
struct PairTab { unsigned short ij[NPAIR]; };  // i*32 + j
static constexpr PairTab make_tab() {
    PairTab t{};
    int p = 0;
    for (int i = 0; i < NF; ++i)
        for (int j = i + 1; j < NF; ++j) { t.ij[p] = (unsigned short)(i * 32 + j); ++p; }
    return t;
}
__constant__ PairTab TAB = make_tab();

__device__ __forceinline__ ull packf2(float lo, float hi) {
    ull u;
    asm("mov.b64 %0, {%1, %2};" : "=l"(u)
        : "r"(__float_as_uint(lo)), "r"(__float_as_uint(hi)));
    return u;
}
__device__ __forceinline__ void fma2(ull& d, ull a, ull b) {
    asm("fma.rn.f32x2 %0, %1, %2, %0;" : "+l"(d) : "l"(a), "l"(b));
}
__device__ __forceinline__ ull mul2(ull a, ull b) {
    ull d; asm("mul.rn.f32x2 %0, %1, %2;" : "=l"(d) : "l"(a), "l"(b)); return d;
}
__device__ __forceinline__ ull add2(ull a, ull b) {
    ull d; asm("add.rn.f32x2 %0, %1, %2;" : "=l"(d) : "l"(a), "l"(b)); return d;
}
__device__ __forceinline__ ull sub2(ull a, ull b) {
    ull d; asm("sub.rn.f32x2 %0, %1, %2;" : "=l"(d) : "l"(a), "l"(b)); return d;
}
__device__ __forceinline__ float lo32(ull u) { return __uint_as_float((unsigned)u); }
__device__ __forceinline__ float hi32(ull u) { return __uint_as_float((unsigned)(u >> 32)); }

// 8 packed outputs for two pairs (offsets pre-folded into B1/B2):
//   acc[q] = ( out_p1[q], out_p2[q] ),  out[n] = sum_k A[k+N] * B[n-k+N]
// Static rotation: at iter k, output q reads w[(q-k)&7]; after iter k, slot
// (7-k)&7 is rebuilt ENTIRELY from two fresh scalar LDS (no old components).
template <int N>
__device__ __forceinline__ void conv8p2(const float* __restrict__ A1,
                                        const float* __restrict__ A2,
                                        const float* __restrict__ B1,
                                        const float* __restrict__ B2,
                                        ull* __restrict__ acc)
{
    ull w[8];
#pragma unroll
    for (int s = 0; s < 8; ++s) w[s] = packf2(B1[N + s], B2[N + s]);

    // k = 0 peeled as mul (no acc zero-init)
    {
        const ull a2 = packf2(A1[N], A2[N]);
#pragma unroll
        for (int q = 0; q < 8; ++q) acc[q] = mul2(a2, w[q]);
        w[7] = packf2(B1[N - 1], B2[N - 1]);
    }
#pragma unroll
    for (int k = 1; k < N; ++k) {
        const ull a2 = packf2(A1[N + k], A2[N + k]);
#pragma unroll
        for (int q = 0; q < 8; ++q) fma2(acc[q], a2, w[(q - k) & 7]);
        if (k < N - 1)
            w[(7 - k) & 7] = packf2(B1[N - 1 - k], B2[N - 1 - k]);
    }
}

__global__ __launch_bounds__(THREADS, 4)
void holo_p2_kernel(const float* __restrict__ in, float* __restrict__ out)
{
    __shared__ float smem[SMEM_FLOATS];
    float* __restrict__ bufV = smem;           // negacyclic-32 operand, scale 1/sqrt2
    float* __restrict__ bufP = smem + OFF_P;   // cyclic-16 operand (dup), scale 1/2
    float* __restrict__ bufQ = smem + OFF_Q;   // negacyclic-16 operand, scale 1/2

    const int batch = blockIdx.x;
    const float* __restrict__ src = in + (size_t)batch * (NF * LEN);
    const int tid = threadIdx.x;

    // ---- per-field folds ----
    for (int idx = tid; idx < NF * 16; idx += THREADS) {
        const int f = idx >> 4, m = idx & 15;
        const float* x = src + f * LEN;
        const float x0 = x[m], x1 = x[m + 16], x2 = x[m + 32], x3 = x[m + 48];
        const float s = 0.70710678118654752f;
        const float vlo = (x0 - x2) * s, vhi = (x1 - x3) * s;
        const float ulo = x0 + x2,       uhi = x1 + x3;
        const float P = (ulo + uhi) * 0.5f, Q = (ulo - uhi) * 0.5f;
        float* bV = bufV + f * SV;
        bV[m]      = -vlo;  bV[m + 16] = -vhi;
        bV[m + 32] =  vlo;  bV[m + 48] =  vhi;
        float* bP = bufP + f * SP;
        bP[m] = P;  bP[m + 16] = P;
        float* bQ = bufQ + f * SP;
        bQ[m] = -Q; bQ[m + 16] = Q;
    }
    __syncthreads();

    // thread -> (duo, role, output-half)
    const int role = (tid >> 1) & 1;
    const int oh   = tid & 1;
    int duo = blockIdx.y * DUOS_PER_BLOCK + (tid >> 2);
    const bool live = (tid < ACTIVE);
    if (duo >= NPAIR / 2) duo = NPAIR / 2 - 1;        // tail duplicates, no store
    const int p1 = 2 * duo, p2 = 2 * duo + 1;
    const int ij1 = TAB.ij[p1], ij2 = TAB.ij[p2];
    const int i1 = ij1 >> 5, j1 = ij1 & 31;
    const int i2 = ij2 >> 5, j2 = ij2 & 31;

    const int n0 = (role << 4) + (oh << 3);           // 0, 8, 16, 24

    // ---- phase 1: negacyclic-32, 8 packed outputs c2[n0..n0+8) ----
    ull av[8];
    conv8p2<32>(bufV + i1 * SV, bufV + i2 * SV,
                bufV + j1 * SV + n0, bufV + j2 * SV + n0, av);

    // ---- phase 2: 16-conv (role0: cyclic P, role1: negacyclic Q),
    //      8 packed outputs d[oh*8 .. +8) ----
    const float* Ab = role ? bufQ : bufP;
    const int m0 = oh << 3;
    ull d[8];
    conv8p2<16>(Ab + i1 * SP, Ab + i2 * SP,
                Ab + j1 * SP + m0, Ab + j2 * SP + m0, d);

    // ---- exchange with role-partner (lane ^ 2), fold into c1, recon, store ----
    // role0: c1[n] = d_P + d_Q (n = m0+q);  role1: c1[n] = d_P - d_Q (n = 16+m0+q)
    if (live) {
        float* __restrict__ o1 = out + ((size_t)batch * NPAIR + p1) * LEN + n0;
        float* __restrict__ o2 = out + ((size_t)batch * NPAIR + p2) * LEN + n0;
#pragma unroll
        for (int g = 0; g < 2; ++g) {
            ull rp[4], rm[4];
#pragma unroll
            for (int r = 0; r < 4; ++r) {
                const int q = 4 * g + r;
                const ull other = __shfl_xor_sync(0xFFFFFFFFu, d[q], 2);
                const ull c1 = role ? sub2(other, d[q]) : add2(d[q], other);
                rp[r] = add2(c1, av[q]);   // out[n0+q]
                rm[r] = sub2(c1, av[q]);   // out[n0+32+q]
            }
            ((float4*)(o1 + 4 * g))[0] =
                make_float4(lo32(rp[0]), lo32(rp[1]), lo32(rp[2]), lo32(rp[3]));
            ((float4*)(o1 + 32 + 4 * g))[0] =
                make_float4(lo32(rm[0]), lo32(rm[1]), lo32(rm[2]), lo32(rm[3]));
            ((float4*)(o2 + 4 * g))[0] =
                make_float4(hi32(rp[0]), hi32(rp[1]), hi32(rp[2]), hi32(rp[3]));
            ((float4*)(o2 + 32 + 4 * g))[0] =
                make_float4(hi32(rm[0]), hi32(rm[1]), hi32(rm[2]), hi32(rm[3]));
        }
    } else {
        // keep shuffles convergent for duplicated tail threads
#pragma unroll
        for (int q = 0; q < 8; ++q)
            (void)__shfl_xor_sync(0xFFFFFFFFu, d[q], 2);
    }
}

extern "C" void kernel_launch(void* const* d_in, const int* in_sizes, int n_in,
                              void* d_out, int out_size)
{
    const float* in  = (const float*)d_in[0];
    float*       out = (float*)d_out;
    const int batches = in_sizes[0] / (NF * LEN);   // 2048 for the bench shape
    dim3 grid(batches, 3);
    holo_p2_kernel<<<grid, THREADS>>>(in, out);
}

// round 17
// speedup vs baseline: 1.0060x; 1.0060x over previous
#include <cuda_runtime.h>
#include <cstdint>

// HolographicFMLayer: batched all-pairs circular convolution.
// inputs: float32 [B, 24, 64]  ->  out: float32 [B, 276, 64]
// out[b,p,n] = sum_k x[b,i,k] * x[b,j,(n-k) mod 64], pairs = triu_indices(24, k=1)
//
// CRT split: x^64-1 = (x^16-1)(x^16+1)(x^32+1)
//   per field: u = lo+hi, v = (lo-hi)/sqrt2; P=(u_lo+u_hi)/2, Q=(u_lo-u_hi)/2
//   per pair : d1 = cyclic16(P), d2 = negacyclic16(Q), c2 = negacyclic32(v)
//   recon    : c1[n<16]=d1+d2, c1[16..31]=d1-d2; out[n<32]=c1+c2, out[n+32]=c1-c2
// 1536 MAC/pair. Scalar FFMA engine (packed f32x2 proven zero-gain on sm_103a:
// R15 halved FMA instrs, fma-pipe% unchanged -> FFMA2 takes 2 pipe slots).
//
// R16: 4 threads/pair for latency coverage. sub = tid&3 = (role<<1)|half:
//   conv32 -> av[8] = c2[8*sub .. +8)          (offset folded into B pointer)
//   conv16 -> d[8]  = (role? negacyc16(Q) : cyclic16(P))[8*half .. +8)
//   exchange shfl_xor(d, 2) (P<->Q partner, same half) -> c1 -> out.
// Small live set (~34 floats) under a 56-reg cap -> 36 warps/SM (was 22).

#define NF 24
#define NPAIR 276
#define LEN 64
#define THREADS 288
#define PAIRS_PER_BLOCK 69      // 4 blocks per batch: 69*4 = 276 exact
#define ACTIVE (PAIRS_PER_BLOCK * 4)   // 276 threads live, 12 tail
#define SV 65                   // 64-entry rows: 65 mod 32 == 1
#define SP 33                   // 32-entry rows: 33 mod 32 == 1
#define OFF_P (NF * SV)                 // 1560
#define OFF_Q (OFF_P + NF * SP + 24)    // +24 pad: (OFF_Q-OFF_P) mod 32 == 16
#define SMEM_FLOATS (OFF_Q + NF * SP)

// constexpr-built triu pair table in constant memory
struct PairTab { unsigned short ij[NPAIR]; };  // i*32 + j
static constexpr PairTab make_tab() {
    PairTab t{};
    int p = 0;
    for (int i = 0; i < NF; ++i)
        for (int j = i + 1; j < NF; ++j) { t.ij[p] = (unsigned short)(i * 32 + j); ++p; }
    return t;
}
__constant__ PairTab TAB = make_tab();

// Length-N convolution, 8 consecutive outputs (offset pre-folded into B):
//   acc[q] = sum_{k=0}^{N-1} A[k+N] * B[q-k+N]
// Scalar sliding window (renames to zero instructions at adequate reg budget).
template <int N>
__device__ __forceinline__ void conv8s(const float* __restrict__ A,
                                       const float* __restrict__ B,
                                       float* __restrict__ acc)
{
    float w[8];
#pragma unroll
    for (int q = 0; q < 8; ++q) w[q] = B[q + N];

    // k = 0 peeled as mul (no acc zero-init)
    {
        const float a = A[N];
#pragma unroll
        for (int q = 0; q < 8; ++q) acc[q] = a * w[q];
        const float nw = B[N - 1];
#pragma unroll
        for (int q = 7; q > 0; --q) w[q] = w[q - 1];
        w[0] = nw;
    }
#pragma unroll
    for (int k = 1; k < N; ++k) {
        const float a = A[N + k];
#pragma unroll
        for (int q = 0; q < 8; ++q) acc[q] = fmaf(a, w[q], acc[q]);
        const float nw = B[N - 1 - k];   // k==N-1 value unused; still in-bounds
#pragma unroll
        for (int q = 7; q > 0; --q) w[q] = w[q - 1];
        w[0] = nw;
    }
}

__global__ __launch_bounds__(THREADS, 4)
void holo_r16_kernel(const float* __restrict__ in, float* __restrict__ out)
{
    __shared__ float smem[SMEM_FLOATS];
    float* __restrict__ bufV = smem;           // negacyclic-32 operand, scale 1/sqrt2
    float* __restrict__ bufP = smem + OFF_P;   // cyclic-16 operand (dup), scale 1/2
    float* __restrict__ bufQ = smem + OFF_Q;   // negacyclic-16 operand, scale 1/2

    const int batch = blockIdx.x;
    const float* __restrict__ src = in + (size_t)batch * (NF * LEN);
    const int tid = threadIdx.x;

    // ---- per-field folds ----
    for (int idx = tid; idx < NF * 16; idx += THREADS) {
        const int f = idx >> 4, m = idx & 15;
        const float* x = src + f * LEN;
        const float x0 = x[m], x1 = x[m + 16], x2 = x[m + 32], x3 = x[m + 48];
        const float s = 0.70710678118654752f;
        const float vlo = (x0 - x2) * s, vhi = (x1 - x3) * s;
        const float ulo = x0 + x2,       uhi = x1 + x3;
        const float P = (ulo + uhi) * 0.5f, Q = (ulo - uhi) * 0.5f;
        float* bV = bufV + f * SV;
        bV[m]      = -vlo;  bV[m + 16] = -vhi;
        bV[m + 32] =  vlo;  bV[m + 48] =  vhi;
        float* bP = bufP + f * SP;
        bP[m] = P;  bP[m + 16] = P;
        float* bQ = bufQ + f * SP;
        bQ[m] = -Q; bQ[m + 16] = Q;
    }
    __syncthreads();

    // thread -> (pair, sub); sub = (role<<1) | half
    const int sub  = tid & 3;
    const int half = sub & 1;
    const int role = sub >> 1;
    int p = blockIdx.y * PAIRS_PER_BLOCK + (tid >> 2);
    const bool live = (tid < ACTIVE);
    if (p >= NPAIR) p = NPAIR - 1;                     // tail duplicates, no store
    const int ij = TAB.ij[p];
    const int i  = ij >> 5;
    const int j  = ij & 31;

    const int n0 = sub << 3;                           // 0, 8, 16, 24

    // ---- phase 1: negacyclic-32, 8 outputs av[q] = c2[n0+q] ----
    // All offsets folded into B pointer: single instantiation, no divergence.
    const float* A32 = bufV + i * SV;
    const float* B32 = bufV + j * SV + n0;
    float av[8];
    conv8s<32>(A32, B32, av);

    // ---- phase 2: role's 16-conv, 8 outputs d[q] = d_role[8*half+q] ----
    const float* A16 = (role ? bufQ : bufP) + i * SP;
    const float* B16 = (role ? bufQ : bufP) + j * SP + (half << 3);
    float d[8];
    conv8s<16>(A16, B16, d);

    // ---- exchange (P<->Q partner: lane ^ 2), fold, reconstruct, store ----
    // role0 (n0 = 8*half):      c1[n0+q] = d_P + d_Q
    // role1 (n0 = 16 + 8*half): c1[n0+q] = d_P - d_Q
    // out[n0+q] = c1 + av,  out[n0+32+q] = c1 - av
    if (live) {
        float* __restrict__ dstf = out + ((size_t)batch * NPAIR + p) * LEN + n0;
#pragma unroll
        for (int g = 0; g < 2; ++g) {
            float rp[4], rm[4];
#pragma unroll
            for (int r = 0; r < 4; ++r) {
                const int q = 4 * g + r;
                const float other = __shfl_xor_sync(0xFFFFFFFFu, d[q], 2);
                const float c1 = role ? (other - d[q]) : (d[q] + other);
                rp[r] = c1 + av[q];
                rm[r] = c1 - av[q];
            }
            ((float4*)(dstf + 4 * g))[0]      = make_float4(rp[0], rp[1], rp[2], rp[3]);
            ((float4*)(dstf + 32 + 4 * g))[0] = make_float4(rm[0], rm[1], rm[2], rm[3]);
        }
    } else {
        // keep shuffles convergent for duplicated tail threads
#pragma unroll
        for (int q = 0; q < 8; ++q)
            (void)__shfl_xor_sync(0xFFFFFFFFu, d[q], 2);
    }
}

extern "C" void kernel_launch(void* const* d_in, const int* in_sizes, int n_in,
                              void* d_out, int out_size)
{
    const float* in  = (const float*)d_in[0];
    float*       out = (float*)d_out;
    const int batches = in_sizes[0] / (NF * LEN);   // 2048 for the bench shape
    dim3 grid(batches, 4);
    holo_r16_kernel<<<grid, THREADS>>>(in, out);
}